// round 1
// baseline (speedup 1.0000x reference)
#include <cuda_runtime.h>

#define TSEQ 2048
#define NTHR 256

// ---------------------------------------------------------------------------
// Fast, accurate nonlinearities: ex2.approx (~2 ulp) + rcp.approx (~2 ulp).
// Deliberately NOT tanh.approx (2^-11 rel err) -- recurrence over 2048 steps
// needs headroom under the 1e-3 threshold.
// ---------------------------------------------------------------------------
__device__ __forceinline__ float fsig(float x) {
    return __fdividef(1.0f, 1.0f + __expf(-x));
}
__device__ __forceinline__ float ftanh_(float x) {
    x = fminf(fmaxf(x, -15.0f), 15.0f);   // avoid inf/inf -> NaN
    float e = __expf(-2.0f * x);
    return __fdividef(1.0f - e, 1.0f + e);
}

// ---------------------------------------------------------------------------
// Shared memory layout (float offsets). H=51 padded to HP=52 (padded weight
// rows/cols are zeroed, so padded lanes compute h=0 forever and contribute 0).
// h arrays use stride 53 (odd) -> conflict-free batched access.
// ---------------------------------------------------------------------------
constexpr int HP    = 52;
constexpr int GPAD  = 208;            // 4*HP gate rows
constexpr int HSTR  = 53;
constexpr int BT    = 64;             // batch per CTA

constexpr int OFF_WHH1 = 0;                        // [208][52]
constexpr int OFF_W2   = OFF_WHH1 + GPAD * HP;     // [208][104]  (W_ih2 | W_hh2)
constexpr int OFF_WX1  = OFF_W2 + GPAD * 104;      // [208]
constexpr int OFF_B1   = OFF_WX1 + GPAD;           // [208]
constexpr int OFF_B2   = OFF_B1 + GPAD;            // [208]
constexpr int OFF_WLIN = OFF_B2 + GPAD;            // [52]
constexpr int OFF_H1   = OFF_WLIN + HP;            // [2][64][53]
constexpr int OFF_H2   = OFF_H1 + 2 * BT * HSTR;   // [2][64][53]
constexpr int OFF_XS   = OFF_H2 + 2 * BT * HSTR;   // [64][33]
constexpr int OFF_OS   = OFF_XS + BT * 33;         // [64][33]
constexpr int SMEM_FLOATS = OFF_OS + BT * 33;
constexpr int SMEM_BYTES  = SMEM_FLOATS * 4;       // ~203.7 KB

__global__ void __launch_bounds__(NTHR, 1) lstm_persist_kernel(
    const float* __restrict__ input,
    const float* __restrict__ W_ih1, const float* __restrict__ W_hh1,
    const float* __restrict__ b_ih1, const float* __restrict__ b_hh1,
    const float* __restrict__ W_ih2, const float* __restrict__ W_hh2,
    const float* __restrict__ b_ih2, const float* __restrict__ b_hh2,
    const float* __restrict__ W_lin, const float* __restrict__ b_lin,
    float* __restrict__ out)
{
    extern __shared__ float sm[];
    const int tid = threadIdx.x;

    // ---- zero weight zone (padding must be 0) + h state buffers ----
    for (int i = tid; i < OFF_H1; i += NTHR) sm[i] = 0.0f;
    for (int i = tid; i < 4 * BT * HSTR; i += NTHR) sm[OFF_H1 + i] = 0.0f;
    __syncthreads();

    // ---- stage weights into padded SMEM layout ----
    // PyTorch gate row r = q*51 + j  ->  padded row rp = q*52 + j
    for (int i = tid; i < 204 * 51; i += NTHR) {
        int r = i / 51, c = i - r * 51;
        int q = r / 51, j = r - q * 51;
        int rp = q * HP + j;
        sm[OFF_WHH1 + rp * HP + c]      = W_hh1[i];
        sm[OFF_W2   + rp * 104 + c]     = W_ih2[i];
        sm[OFF_W2   + rp * 104 + HP + c]= W_hh2[i];
    }
    for (int i = tid; i < 204; i += NTHR) {
        int q = i / 51, j = i - q * 51;
        int rp = q * HP + j;
        sm[OFF_WX1 + rp] = W_ih1[i];
        sm[OFF_B1  + rp] = b_ih1[i] + b_hh1[i];
        sm[OFF_B2  + rp] = b_ih2[i] + b_hh2[i];
    }
    if (tid < 51) sm[OFF_WLIN + tid] = W_lin[tid];
    __syncthreads();

    // ---- thread mapping: warp-uniform chunk => broadcast weight loads ----
    const int chunk = tid >> 6;          // 0..3 (uniform within a warp)
    const int bl    = tid & 63;          // batch-local 0..63
    const int j0    = chunk * 13;        // this thread's 13 hidden indices
    const float blin = b_lin[0];

    float c1[13], c2[13];
#pragma unroll
    for (int jj = 0; jj < 13; jj++) { c1[jj] = 0.0f; c2[jj] = 0.0f; }

    const size_t growbase = (size_t)(blockIdx.x * BT) * TSEQ;
    int cur = 0;

#pragma unroll 1
    for (int t0 = 0; t0 < TSEQ; t0 += 32) {
        // ---- stage 64x32 input tile (coalesced 128B per warp) ----
#pragma unroll
        for (int rep = 0; rep < 8; rep++) {
            int idx = tid + rep * NTHR;
            int rb = idx >> 5, cc = idx & 31;
            sm[OFF_XS + rb * 33 + cc] = input[growbase + (size_t)rb * TSEQ + t0 + cc];
        }
        __syncthreads();

#pragma unroll 1
        for (int ti = 0; ti < 32; ti++) {
            const float xb = sm[OFF_XS + bl * 33 + ti];
            float acc[52];

            // ================= layer 1 gates =================
#pragma unroll
            for (int q = 0; q < 4; q++)
#pragma unroll
                for (int jj = 0; jj < 13; jj++) {
                    int rp = q * HP + j0 + jj;
                    acc[q * 13 + jj] = fmaf(sm[OFF_WX1 + rp], xb, sm[OFF_B1 + rp]);
                }
            {
                const float* h1c = sm + OFF_H1 + cur * (BT * HSTR) + bl * HSTR;
#pragma unroll 1
                for (int k4 = 0; k4 < HP; k4 += 4) {
                    float hv0 = h1c[k4 + 0], hv1 = h1c[k4 + 1];
                    float hv2 = h1c[k4 + 2], hv3 = h1c[k4 + 3];
#pragma unroll
                    for (int q = 0; q < 4; q++)
#pragma unroll
                        for (int jj = 0; jj < 13; jj++) {
                            const float4 w = *(const float4*)(sm + OFF_WHH1 + (q * HP + j0 + jj) * HP + k4);
                            float a = acc[q * 13 + jj];
                            a = fmaf(w.x, hv0, a);
                            a = fmaf(w.y, hv1, a);
                            a = fmaf(w.z, hv2, a);
                            a = fmaf(w.w, hv3, a);
                            acc[q * 13 + jj] = a;
                        }
                }
            }
            float* h1n = sm + OFF_H1 + (cur ^ 1) * (BT * HSTR) + bl * HSTR;
#pragma unroll
            for (int jj = 0; jj < 13; jj++) {
                float iv = fsig(acc[jj]);
                float fv = fsig(acc[13 + jj]);
                float gv = ftanh_(acc[26 + jj]);
                float ov = fsig(acc[39 + jj]);
                float cn = fmaf(fv, c1[jj], iv * gv);
                c1[jj] = cn;
                h1n[j0 + jj] = ov * ftanh_(cn);
            }
            __syncthreads();   // h1(new) visible to all

            // ================= layer 2 gates =================
#pragma unroll
            for (int q = 0; q < 4; q++)
#pragma unroll
                for (int jj = 0; jj < 13; jj++)
                    acc[q * 13 + jj] = sm[OFF_B2 + q * HP + j0 + jj];
            {
                // K-part 1: h1(new)
#pragma unroll 1
                for (int k4 = 0; k4 < HP; k4 += 4) {
                    float hv0 = h1n[k4 + 0], hv1 = h1n[k4 + 1];
                    float hv2 = h1n[k4 + 2], hv3 = h1n[k4 + 3];
#pragma unroll
                    for (int q = 0; q < 4; q++)
#pragma unroll
                        for (int jj = 0; jj < 13; jj++) {
                            const float4 w = *(const float4*)(sm + OFF_W2 + (q * HP + j0 + jj) * 104 + k4);
                            float a = acc[q * 13 + jj];
                            a = fmaf(w.x, hv0, a);
                            a = fmaf(w.y, hv1, a);
                            a = fmaf(w.z, hv2, a);
                            a = fmaf(w.w, hv3, a);
                            acc[q * 13 + jj] = a;
                        }
                }
                // K-part 2: h2(prev)
                const float* h2c = sm + OFF_H2 + cur * (BT * HSTR) + bl * HSTR;
#pragma unroll 1
                for (int k4 = 0; k4 < HP; k4 += 4) {
                    float hv0 = h2c[k4 + 0], hv1 = h2c[k4 + 1];
                    float hv2 = h2c[k4 + 2], hv3 = h2c[k4 + 3];
#pragma unroll
                    for (int q = 0; q < 4; q++)
#pragma unroll
                        for (int jj = 0; jj < 13; jj++) {
                            const float4 w = *(const float4*)(sm + OFF_W2 + (q * HP + j0 + jj) * 104 + HP + k4);
                            float a = acc[q * 13 + jj];
                            a = fmaf(w.x, hv0, a);
                            a = fmaf(w.y, hv1, a);
                            a = fmaf(w.z, hv2, a);
                            a = fmaf(w.w, hv3, a);
                            acc[q * 13 + jj] = a;
                        }
                }
            }
            float* h2n = sm + OFF_H2 + (cur ^ 1) * (BT * HSTR) + bl * HSTR;
#pragma unroll
            for (int jj = 0; jj < 13; jj++) {
                float iv = fsig(acc[jj]);
                float fv = fsig(acc[13 + jj]);
                float gv = ftanh_(acc[26 + jj]);
                float ov = fsig(acc[39 + jj]);
                float cn = fmaf(fv, c2[jj], iv * gv);
                c2[jj] = cn;
                h2n[j0 + jj] = ov * ftanh_(cn);
            }
            __syncthreads();   // h2(new) visible

            // ---- output projection (warps 0-1 only; ~160 instrs) ----
            if (chunk == 0) {
                float s = blin;
#pragma unroll
                for (int k = 0; k < 51; k++)
                    s = fmaf(sm[OFF_WLIN + k], h2n[k], s);
                sm[OFF_OS + bl * 33 + ti] = s;
            }
            cur ^= 1;
        }
        __syncthreads();

        // ---- flush 64x32 output tile (coalesced) ----
#pragma unroll
        for (int rep = 0; rep < 8; rep++) {
            int idx = tid + rep * NTHR;
            int rb = idx >> 5, cc = idx & 31;
            out[growbase + (size_t)rb * TSEQ + t0 + cc] = sm[OFF_OS + rb * 33 + cc];
        }
    }
}

extern "C" void kernel_launch(void* const* d_in, const int* in_sizes, int n_in,
                              void* d_out, int out_size) {
    const float* input = (const float*)d_in[0];
    const float* W_ih1 = (const float*)d_in[1];
    const float* W_hh1 = (const float*)d_in[2];
    const float* b_ih1 = (const float*)d_in[3];
    const float* b_hh1 = (const float*)d_in[4];
    const float* W_ih2 = (const float*)d_in[5];
    const float* W_hh2 = (const float*)d_in[6];
    const float* b_ih2 = (const float*)d_in[7];
    const float* b_hh2 = (const float*)d_in[8];
    const float* W_lin = (const float*)d_in[9];
    const float* b_lin = (const float*)d_in[10];
    float* out = (float*)d_out;

    const int B = in_sizes[0] / TSEQ;     // 8192
    const int grid = B / BT;              // 128 persistent CTAs

    cudaFuncSetAttribute(lstm_persist_kernel,
                         cudaFuncAttributeMaxDynamicSharedMemorySize, SMEM_BYTES);

    lstm_persist_kernel<<<grid, NTHR, SMEM_BYTES>>>(
        input, W_ih1, W_hh1, b_ih1, b_hh1,
        W_ih2, W_hh2, b_ih2, b_hh2, W_lin, b_lin, out);
}

// round 2
// speedup vs baseline: 1.0696x; 1.0696x over previous
#include <cuda_runtime.h>

#define TSEQ 2048
#define NTHR 256
#define BT   64

typedef unsigned long long u64;

// ---------------------------------------------------------------------------
// Packed f32x2 helpers (Blackwell). ptxas never auto-fuses FFMA2 from C++;
// it only exists via PTX fma.rn.f32x2.
// ---------------------------------------------------------------------------
__device__ __forceinline__ void ffma2(u64& d, u64 a, u64 b) {
    asm("fma.rn.f32x2 %0, %1, %2, %0;" : "+l"(d) : "l"(a), "l"(b));
}
__device__ __forceinline__ u64 ffma2_o(u64 a, u64 b, u64 c) {
    u64 d; asm("fma.rn.f32x2 %0, %1, %2, %3;" : "=l"(d) : "l"(a), "l"(b), "l"(c));
    return d;
}
__device__ __forceinline__ u64 pack2(float lo, float hi) {
    u64 r; asm("mov.b64 %0, {%1, %2};" : "=l"(r) : "f"(lo), "f"(hi)); return r;
}
__device__ __forceinline__ void unpack2(u64 v, float& lo, float& hi) {
    asm("mov.b64 {%0, %1}, %2;" : "=f"(lo), "=f"(hi) : "l"(v));
}

// Accurate-enough nonlinearities: ex2.approx + rcp.approx (~2 ulp each).
__device__ __forceinline__ float fsig(float x) {
    return __fdividef(1.0f, 1.0f + __expf(-x));
}
__device__ __forceinline__ float ftanh_(float x) {
    x = fminf(fmaxf(x, -15.0f), 15.0f);
    float e = __expf(-2.0f * x);
    return __fdividef(1.0f - e, 1.0f + e);
}

// ---------------------------------------------------------------------------
// SMEM layout (float indices). H=51 padded to HP=52 (padding zeroed).
// Weights interleaved [j][k][gate q=0..3] -> one LDS.128 = packed (i,f),(g,o).
// h stored DUPLICATED as [k][batch][2] -> one LDS.64 = dup'd h operand.
// ---------------------------------------------------------------------------
constexpr int HP = 52;

constexpr int OFF_W1   = 0;                         // [52][52][4]  = 10816
constexpr int OFF_W2   = OFF_W1 + 52 * 52 * 4;      // [52][104][4] = 21632
constexpr int OFF_WXIF = OFF_W2 + 52 * 104 * 4;     // [52][2]
constexpr int OFF_WXGO = OFF_WXIF + 104;
constexpr int OFF_BIF1 = OFF_WXGO + 104;
constexpr int OFF_BGO1 = OFF_BIF1 + 104;
constexpr int OFF_BIF2 = OFF_BGO1 + 104;
constexpr int OFF_BGO2 = OFF_BIF2 + 104;
constexpr int OFF_WLIN = OFF_BGO2 + 104;            // [52]
constexpr int OFF_H1   = OFF_WLIN + 52;             // [52][64][2] = 6656 (even ✓)
constexpr int OFF_H2   = OFF_H1 + 52 * BT * 2;      // 6656
constexpr int OFF_XS   = OFF_H2 + 52 * BT * 2;      // [64][33] = 2112
constexpr int OFF_OS   = OFF_XS + BT * 33;          // 2112
constexpr int OFF_PART = OFF_OS + BT * 33;          // [4][64]
constexpr int SMEM_FLOATS = OFF_PART + 4 * BT;
constexpr int SMEM_BYTES  = SMEM_FLOATS * 4;        // ~203.7 KB

__global__ void __launch_bounds__(NTHR, 1) lstm_f32x2_kernel(
    const float* __restrict__ input,
    const float* __restrict__ W_ih1, const float* __restrict__ W_hh1,
    const float* __restrict__ b_ih1, const float* __restrict__ b_hh1,
    const float* __restrict__ W_ih2, const float* __restrict__ W_hh2,
    const float* __restrict__ b_ih2, const float* __restrict__ b_hh2,
    const float* __restrict__ W_lin, const float* __restrict__ b_lin,
    float* __restrict__ out)
{
    extern __shared__ float sm[];
    const int tid = threadIdx.x;

    // ---- zero everything up to XS (weight padding + h/c state) ----
    for (int i = tid; i < OFF_XS; i += NTHR) sm[i] = 0.0f;
    __syncthreads();

    // ---- stage weights: gate-interleaved [j][k][q] ----
    for (int i = tid; i < 4 * 51 * 51; i += NTHR) {
        int q = i / (51 * 51), rem = i - q * 51 * 51;
        int j = rem / 51, c = rem - j * 51;
        float whh1 = W_hh1[(q * 51 + j) * 51 + c];
        float wih2 = W_ih2[(q * 51 + j) * 51 + c];
        float whh2 = W_hh2[(q * 51 + j) * 51 + c];
        sm[OFF_W1 + j * 208 + c * 4 + q]        = whh1;
        sm[OFF_W2 + j * 416 + c * 4 + q]        = wih2;
        sm[OFF_W2 + j * 416 + (52 + c) * 4 + q] = whh2;
    }
    for (int j = tid; j < 51; j += NTHR) {
        sm[OFF_WXIF + j * 2 + 0] = W_ih1[j];
        sm[OFF_WXIF + j * 2 + 1] = W_ih1[51 + j];
        sm[OFF_WXGO + j * 2 + 0] = W_ih1[102 + j];
        sm[OFF_WXGO + j * 2 + 1] = W_ih1[153 + j];
        sm[OFF_BIF1 + j * 2 + 0] = b_ih1[j]       + b_hh1[j];
        sm[OFF_BIF1 + j * 2 + 1] = b_ih1[51 + j]  + b_hh1[51 + j];
        sm[OFF_BGO1 + j * 2 + 0] = b_ih1[102 + j] + b_hh1[102 + j];
        sm[OFF_BGO1 + j * 2 + 1] = b_ih1[153 + j] + b_hh1[153 + j];
        sm[OFF_BIF2 + j * 2 + 0] = b_ih2[j]       + b_hh2[j];
        sm[OFF_BIF2 + j * 2 + 1] = b_ih2[51 + j]  + b_hh2[51 + j];
        sm[OFF_BGO2 + j * 2 + 0] = b_ih2[102 + j] + b_hh2[102 + j];
        sm[OFF_BGO2 + j * 2 + 1] = b_ih2[153 + j] + b_hh2[153 + j];
        sm[OFF_WLIN + j] = W_lin[j];
    }
    __syncthreads();

    // ---- thread mapping: warp-uniform chunk => broadcast weight loads ----
    const int chunk = tid >> 6;           // 0..3, uniform within a warp
    const int bl    = tid & 63;           // batch-local, consecutive per lane
    const int j0    = chunk * 13;
    const float blin = b_lin[0];

    float c1[13], c2[13];
#pragma unroll
    for (int jj = 0; jj < 13; jj++) { c1[jj] = 0.0f; c2[jj] = 0.0f; }

    const size_t growbase = (size_t)(blockIdx.x * BT) * TSEQ;

    const float* __restrict__ h1b = sm + OFF_H1 + bl * 2;   // [k][bl][2]
    const float* __restrict__ h2b = sm + OFF_H2 + bl * 2;

#pragma unroll 1
    for (int t0 = 0; t0 < TSEQ; t0 += 32) {
        // stage 64x32 input tile (coalesced)
#pragma unroll
        for (int rep = 0; rep < 8; rep++) {
            int idx = tid + rep * NTHR;
            int rb = idx >> 5, cc = idx & 31;
            sm[OFF_XS + rb * 33 + cc] = input[growbase + (size_t)rb * TSEQ + t0 + cc];
        }
        __syncthreads();

#pragma unroll 1
        for (int ti = 0; ti < 32; ti++) {
            const float xb = sm[OFF_XS + bl * 33 + ti];
            const u64 xdup = pack2(xb, xb);

            u64 aif[13], ago[13];

            // ======== layer 1 gates: acc = Wx*x + b + Whh*h1 ========
#pragma unroll
            for (int jj = 0; jj < 13; jj++) {
                int j = j0 + jj;
                aif[jj] = ffma2_o(*(const u64*)(sm + OFF_WXIF + j * 2), xdup,
                                  *(const u64*)(sm + OFF_BIF1 + j * 2));
                ago[jj] = ffma2_o(*(const u64*)(sm + OFF_WXGO + j * 2), xdup,
                                  *(const u64*)(sm + OFF_BGO1 + j * 2));
            }
#pragma unroll 2
            for (int k = 0; k < HP; k++) {
                const u64 hd = *(const u64*)(h1b + k * (BT * 2));
#pragma unroll
                for (int jj = 0; jj < 13; jj++) {
                    const ulonglong2 w = *(const ulonglong2*)(sm + OFF_W1 + (j0 + jj) * 208 + k * 4);
                    ffma2(aif[jj], w.x, hd);   // (i,f)
                    ffma2(ago[jj], w.y, hd);   // (g,o)
                }
            }
            __syncthreads();   // all reads of h1(prev) done

            // epilogue 1: write h1(new), duplicated
            {
                float* h1w = sm + OFF_H1 + bl * 2;
#pragma unroll
                for (int jj = 0; jj < 13; jj++) {
                    float ip, fp, gp, op;
                    unpack2(aif[jj], ip, fp);
                    unpack2(ago[jj], gp, op);
                    float cn = fmaf(fsig(fp), c1[jj], fsig(ip) * ftanh_(gp));
                    c1[jj] = cn;
                    float hv = fsig(op) * ftanh_(cn);
                    *(float2*)(h1w + (j0 + jj) * (BT * 2)) = make_float2(hv, hv);
                }
            }
            __syncthreads();   // h1(new) visible

            // ======== layer 2 gates: acc = b + Wih2*h1new + Whh2*h2 ========
#pragma unroll
            for (int jj = 0; jj < 13; jj++) {
                int j = j0 + jj;
                aif[jj] = *(const u64*)(sm + OFF_BIF2 + j * 2);
                ago[jj] = *(const u64*)(sm + OFF_BGO2 + j * 2);
            }
#pragma unroll 2
            for (int k = 0; k < HP; k++) {
                const u64 hd = *(const u64*)(h1b + k * (BT * 2));
#pragma unroll
                for (int jj = 0; jj < 13; jj++) {
                    const ulonglong2 w = *(const ulonglong2*)(sm + OFF_W2 + (j0 + jj) * 416 + k * 4);
                    ffma2(aif[jj], w.x, hd);
                    ffma2(ago[jj], w.y, hd);
                }
            }
#pragma unroll 2
            for (int k = 0; k < HP; k++) {
                const u64 hd = *(const u64*)(h2b + k * (BT * 2));
#pragma unroll
                for (int jj = 0; jj < 13; jj++) {
                    const ulonglong2 w = *(const ulonglong2*)(sm + OFF_W2 + (j0 + jj) * 416 + (52 + k) * 4);
                    ffma2(aif[jj], w.x, hd);
                    ffma2(ago[jj], w.y, hd);
                }
            }
            __syncthreads();   // all reads of h2(prev) done

            // epilogue 2: write h2(new) + partial output dot
            {
                float* h2w = sm + OFF_H2 + bl * 2;
                float s = 0.0f;
#pragma unroll
                for (int jj = 0; jj < 13; jj++) {
                    float ip, fp, gp, op;
                    unpack2(aif[jj], ip, fp);
                    unpack2(ago[jj], gp, op);
                    float cn = fmaf(fsig(fp), c2[jj], fsig(ip) * ftanh_(gp));
                    c2[jj] = cn;
                    float hv = fsig(op) * ftanh_(cn);
                    *(float2*)(h2w + (j0 + jj) * (BT * 2)) = make_float2(hv, hv);
                    s = fmaf(sm[OFF_WLIN + j0 + jj], hv, s);
                }
                sm[OFF_PART + chunk * BT + bl] = s;
            }
            __syncthreads();   // h2(new) + partials visible

            if (chunk == 0) {
                float o = blin
                        + sm[OFF_PART + bl] + sm[OFF_PART + BT + bl]
                        + sm[OFF_PART + 2 * BT + bl] + sm[OFF_PART + 3 * BT + bl];
                sm[OFF_OS + bl * 33 + ti] = o;
            }
        }
        __syncthreads();

        // flush 64x32 output tile (coalesced)
#pragma unroll
        for (int rep = 0; rep < 8; rep++) {
            int idx = tid + rep * NTHR;
            int rb = idx >> 5, cc = idx & 31;
            out[growbase + (size_t)rb * TSEQ + t0 + cc] = sm[OFF_OS + rb * 33 + cc];
        }
    }
}

extern "C" void kernel_launch(void* const* d_in, const int* in_sizes, int n_in,
                              void* d_out, int out_size) {
    const float* input = (const float*)d_in[0];
    const float* W_ih1 = (const float*)d_in[1];
    const float* W_hh1 = (const float*)d_in[2];
    const float* b_ih1 = (const float*)d_in[3];
    const float* b_hh1 = (const float*)d_in[4];
    const float* W_ih2 = (const float*)d_in[5];
    const float* W_hh2 = (const float*)d_in[6];
    const float* b_ih2 = (const float*)d_in[7];
    const float* b_hh2 = (const float*)d_in[8];
    const float* W_lin = (const float*)d_in[9];
    const float* b_lin = (const float*)d_in[10];
    float* out = (float*)d_out;

    const int B = in_sizes[0] / TSEQ;     // 8192
    const int grid = B / BT;              // 128 persistent CTAs

    cudaFuncSetAttribute(lstm_f32x2_kernel,
                         cudaFuncAttributeMaxDynamicSharedMemorySize, SMEM_BYTES);

    lstm_f32x2_kernel<<<grid, NTHR, SMEM_BYTES>>>(
        input, W_ih1, W_hh1, b_ih1, b_hh1,
        W_ih2, W_hh2, b_ih2, b_hh2, W_lin, b_lin, out);
}